// round 8
// baseline (speedup 1.0000x reference)
#include <cuda_runtime.h>
#include <math.h>

// SDF2: mesh -> voxel (inside ? distance : 0) grid. Round-8:
//   - fma-pipe wall broken via Blackwell packed f32x2 (fma/mul/add.rn.f32x2):
//     z-points processed in pairs, all FMA-pipe math packed (2 lanes/inst),
//     clamps/mins/compares stay scalar on register halves (alu pipe, free unpack)
//   - packed broadcast constants pre-duplicated in smem (LDS.64 direct load)
//   - 592 blocks = 148 SMs x 4 (128 thr), 37 balanced triangle chunks
//   - RED atomics reduce (atomicMin on float bits, atomicXor parity)

#define G_DIM    32
#define N_PTS    (G_DIM * G_DIM * G_DIM)          // 32768
#define N_FACES  2048
#define N_CHUNKS 37
#define TRI_MAX  56
#define KPT      16
#define NPAIR    (KPT / 2)
#define N_GROUPS (N_PTS / KPT)                    // 2048
#define THREADS  128
#define EPSF     1e-12f

typedef unsigned long long u64;

__device__ __forceinline__ u64 pk2(float lo, float hi) {
    u64 r; asm("mov.b64 %0, {%1, %2};" : "=l"(r) : "f"(lo), "f"(hi)); return r;
}
__device__ __forceinline__ void up2(u64 v, float& lo, float& hi) {
    asm("mov.b64 {%0, %1}, %2;" : "=f"(lo), "=f"(hi) : "l"(v));
}
__device__ __forceinline__ u64 fma2(u64 a, u64 b, u64 c) {
    u64 r; asm("fma.rn.f32x2 %0, %1, %2, %3;" : "=l"(r) : "l"(a), "l"(b), "l"(c)); return r;
}
__device__ __forceinline__ u64 mul2(u64 a, u64 b) {
    u64 r; asm("mul.rn.f32x2 %0, %1, %2;" : "=l"(r) : "l"(a), "l"(b)); return r;
}
__device__ __forceinline__ u64 add2(u64 a, u64 b) {
    u64 r; asm("add.rn.f32x2 %0, %1, %2;" : "=l"(r) : "l"(a), "l"(b)); return r;
}
__device__ __forceinline__ float clamp01(float x) {
    return fminf(fmaxf(x, 0.0f), 1.0f);
}

__device__ unsigned g_md2min[N_PTS];              // float bits, monotone (md2 >= 0)
__device__ unsigned g_parity[N_GROUPS];           // 16 parity bits per word

__global__ void __launch_bounds__(256)
sdf_init()
{
    int i = blockIdx.x * 256 + threadIdx.x;
    if (i < N_PTS)    g_md2min[i] = 0x7F800000u;  // +inf
    if (i < N_GROUPS) g_parity[i] = 0u;
}

__global__ void __launch_bounds__(THREADS, 4)
sdf_main(const int* __restrict__ faces, const float* __restrict__ verts)
{
    // scalar section: 8 float4 / triangle (same as round 7)
    // 0: ab.xyz, inv_ab   1: ac.xyz, inv_ac   2: bc.xyz, inv_bc
    // 3: A.xyz, kbc       4: B.xyz, inv_n     5: C.xyz, gram
    // 6: n.xyz, qab       7: qaa, qac, ivb, ivc
    __shared__ float4 tc[8 * TRI_MAX];            // 7.2 KB
    // packed (duplicated) section: 18 u64 / triangle
    // 0..8: -ab,-ac,-bc (xyz)   9..11: inv_ab, inv_ac, inv_bc
    // 12..17: iab2, iac2, i432, ihs2, ivb2, ivc2  (all doubled z-steps)
    __shared__ u64 tp[18 * TRI_MAX];              // 8.1 KB

    const int start = (blockIdx.y * N_FACES) / N_CHUNKS;
    const int end   = ((blockIdx.y + 1) * N_FACES) / N_CHUNKS;
    const int ntri  = end - start;
    const float dz  = 1.0f / (float)G_DIM;

    // ---- staging: one thread per triangle computes all constants ----
    if (threadIdx.x < ntri) {
        const int f = threadIdx.x;
        const int base = (start + f) * 3;
        const float* va  = verts + 3 * faces[base + 0];
        const float* vbv = verts + 3 * faces[base + 1];
        const float* vcv = verts + 3 * faces[base + 2];
        float Ax = va[0],  Ay = va[1],  Az = va[2];
        float Bx = vbv[0], By = vbv[1], Bz = vbv[2];
        float Cx = vcv[0], Cy = vcv[1], Cz = vcv[2];

        float abx = Bx - Ax, aby = By - Ay, abz = Bz - Az;
        float acx = Cx - Ax, acy = Cy - Ay, acz = Cz - Az;
        float bcx = Cx - Bx, bcy = Cy - By, bcz = Cz - Bz;

        float qaa = abx * abx + aby * aby + abz * abz;
        float qab = abx * acx + aby * acy + abz * acz;
        float qac = acx * acx + acy * acy + acz * acz;
        float qbc = bcx * bcx + bcy * bcy + bcz * bcz;

        float nx = aby * acz - abz * acy;
        float ny = abz * acx - abx * acz;
        float nz = abx * acy - aby * acx;
        float gram = nx * nx + ny * ny + nz * nz;

        float inv_ab = __fdividef(1.0f, fmaxf(qaa, EPSF));
        float inv_ac = __fdividef(1.0f, fmaxf(qac, EPSF));
        float inv_bc = __fdividef(1.0f, fmaxf(qbc, EPSF));
        float inv_n  = rsqrtf(fmaxf(gram, EPSF));
        float ivb = (qac * abz - qab * acz) * dz;
        float ivc = (qaa * acz - qab * abz) * dz;
        float iab = abz * dz, iac = acz * dz;

        tc[8 * f + 0] = make_float4(abx, aby, abz, inv_ab);
        tc[8 * f + 1] = make_float4(acx, acy, acz, inv_ac);
        tc[8 * f + 2] = make_float4(bcx, bcy, bcz, inv_bc);
        tc[8 * f + 3] = make_float4(Ax, Ay, Az, qaa - qab);   // kbc
        tc[8 * f + 4] = make_float4(Bx, By, Bz, inv_n);
        tc[8 * f + 5] = make_float4(Cx, Cy, Cz, gram);
        tc[8 * f + 6] = make_float4(nx, ny, nz, qab);
        tc[8 * f + 7] = make_float4(qaa, qac, ivb, ivc);

        u64* p = tp + 18 * f;
        p[0]  = pk2(-abx, -abx); p[1]  = pk2(-aby, -aby); p[2]  = pk2(-abz, -abz);
        p[3]  = pk2(-acx, -acx); p[4]  = pk2(-acy, -acy); p[5]  = pk2(-acz, -acz);
        p[6]  = pk2(-bcx, -bcx); p[7]  = pk2(-bcy, -bcy); p[8]  = pk2(-bcz, -bcz);
        p[9]  = pk2(inv_ab, inv_ab); p[10] = pk2(inv_ac, inv_ac); p[11] = pk2(inv_bc, inv_bc);
        p[12] = pk2(2.0f * iab, 2.0f * iab);
        p[13] = pk2(2.0f * iac, 2.0f * iac);
        p[14] = pk2(2.0f * (iac - iab), 2.0f * (iac - iab));
        float ihs = nz * dz * inv_n;
        p[15] = pk2(2.0f * ihs, 2.0f * ihs);
        p[16] = pk2(2.0f * ivb, 2.0f * ivb);
        p[17] = pk2(2.0f * ivc, 2.0f * ivc);
    }
    __syncthreads();

    const int g   = blockIdx.x * THREADS + threadIdx.x;   // [0, 2048)
    const int ix  = g >> 6;
    const int iy  = (g >> 1) & 31;
    const int iz0 = (g & 1) << 4;

    const float px  = ((float)ix  + 0.5f) * dz;
    const float py  = ((float)iy  + 0.5f) * dz;
    const float pz0 = ((float)iz0 + 0.5f) * dz;
    const u64 DZ2 = pk2(2.0f * dz, 2.0f * dz);

    float md[KPT];
    #pragma unroll
    for (int k = 0; k < KPT; ++k) md[k] = INFINITY;
    unsigned par = 0u;

    for (int f = 0; f < ntri; ++f) {
        const float4 c0 = tc[8 * f + 0];
        const float4 c1 = tc[8 * f + 1];
        const float4 c3 = tc[8 * f + 3];
        const float4 c4 = tc[8 * f + 4];
        const float4 c5 = tc[8 * f + 5];
        const float4 c6 = tc[8 * f + 6];
        const float4 c7 = tc[8 * f + 7];
        const float gram = c5.w;
        const u64* p = tp + 18 * f;

        // ---- scalar per-thread init (z-invariant parts) ----
        const float apx = px - c3.x, apy = py - c3.y;
        const float bpx = px - c4.x, bpy = py - c4.y;
        const float apz0 = pz0 - c3.z;
        const float bpz0 = pz0 - c4.z;
        const float iab = c0.z * dz, iac = c1.z * dz;
        float d1a = c0.x * apx + c0.y * apy + c0.z * apz0;    // ab.ap
        float d2a = c1.x * apx + c1.y * apy + c1.z * apz0;    // ac.ap
        float d43a = (d2a - d1a) + c3.w;                      // bp.bc
        float hsa = (c6.x * apx + c6.y * apy + c6.z * apz0) * c4.w;
        float vba = c7.y * d1a - c6.w * d2a;                  // qac*d1 - qab*d2
        float vca = c7.x * d2a - c6.w * d1a;                  // qaa*d2 - qab*d1
        const float ihs = c6.z * dz * c4.w;

        // packed state: lanes = (z_k, z_{k+1})
        u64 D1  = pk2(d1a,  d1a + iab);
        u64 D2  = pk2(d2a,  d2a + iac);
        u64 D43 = pk2(d43a, d43a + (iac - iab));
        u64 APZ = pk2(apz0, apz0 + dz);
        u64 BPZ = pk2(bpz0, bpz0 + dz);
        u64 HS  = pk2(hsa,  hsa + ihs);
        u64 VB  = pk2(vba,  vba + c7.z);
        u64 VC  = pk2(vca,  vca + c7.w);
        // packed constants (duplicated in smem -> one LDS.64 each)
        const u64 NABX = p[0], NABY = p[1], NABZ = p[2];
        const u64 NACX = p[3], NACY = p[4], NACZ = p[5];
        const u64 NBCX = p[6], NBCY = p[7], NBCZ = p[8];
        const u64 IVAB = p[9], IVAC = p[10], IVBC = p[11];
        const u64 IAB2 = p[12], IAC2 = p[13], I432 = p[14];
        const u64 IHS2 = p[15], IVB2 = p[16], IVC2 = p[17];
        const u64 APX = pk2(apx, apx), APY = pk2(apy, apy);
        const u64 BPX = pk2(bpx, bpx), BPY = pk2(bpy, bpy);

        // ---- ray crossing (den == nz), fully hoisted ----
        {
            float cpx2 = px - c5.x, cpy2 = py - c5.y;
            float nz = c6.z;
            float e0 = c4.y - c5.y;
            float e1 = c5.x - c4.x;
            float un = e0 * cpx2 + e1 * cpy2;
            float vn = (c5.y - c3.y) * cpx2 + (c3.x - c5.x) * cpy2;
            float wn = nz - un - vn;
            bool c2d = (fabsf(nz) >= EPSF)
                     & (un * nz >= 0.0f) & (vn * nz >= 0.0f) & (wn * nz >= 0.0f);
            if (c2d) {
                float zhit = __fdividef(un * c3.z + vn * c4.z + wn * c5.z, nz);
                float fcnt = (zhit - pz0) * (float)G_DIM;
                int n = (int)ceilf(fminf(fmaxf(fcnt, 0.0f), (float)KPT));
                par ^= (1u << n) - 1u;
            }
        }

        #pragma unroll
        for (int j = 0; j < NPAIR; ++j) {
            float t0, t1;
            // AB segment
            up2(mul2(D1, IVAB), t0, t1);
            u64 T = pk2(clamp01(t0), clamp01(t1));
            u64 RX = fma2(T, NABX, APX);
            u64 RY = fma2(T, NABY, APY);
            u64 RZ = fma2(T, NABZ, APZ);
            u64 S = mul2(RX, RX); S = fma2(RY, RY, S); S = fma2(RZ, RZ, S);
            float dAB0, dAB1; up2(S, dAB0, dAB1);
            // AC segment
            up2(mul2(D2, IVAC), t0, t1);
            T = pk2(clamp01(t0), clamp01(t1));
            RX = fma2(T, NACX, APX);
            RY = fma2(T, NACY, APY);
            RZ = fma2(T, NACZ, APZ);
            S = mul2(RX, RX); S = fma2(RY, RY, S); S = fma2(RZ, RZ, S);
            float dAC0, dAC1; up2(S, dAC0, dAC1);
            // BC segment
            up2(mul2(D43, IVBC), t0, t1);
            T = pk2(clamp01(t0), clamp01(t1));
            RX = fma2(T, NBCX, BPX);
            RY = fma2(T, NBCY, BPY);
            RZ = fma2(T, NBCZ, BPZ);
            S = mul2(RX, RX); S = fma2(RY, RY, S); S = fma2(RZ, RZ, S);
            float dBC0, dBC1; up2(S, dBC0, dBC1);

            float m0 = fminf(fminf(dAB0, dAC0), dBC0);
            float m1 = fminf(fminf(dAB1, dAC1), dBC1);

            // interior: strict test (degenerate gram==0 excluded)
            float hh0, hh1; up2(mul2(HS, HS), hh0, hh1);
            float s0, s1;   up2(add2(VB, VC), s0, s1);
            float vb0, vb1; up2(VB, vb0, vb1);
            float vc0, vc1; up2(VC, vc0, vc1);
            if ((vb0 > 0.0f) & (vc0 > 0.0f) & (s0 < gram)) m0 = hh0;
            if ((vb1 > 0.0f) & (vc1 > 0.0f) & (s1 < gram)) m1 = hh1;

            md[2 * j]     = fminf(md[2 * j],     m0);
            md[2 * j + 1] = fminf(md[2 * j + 1], m1);

            // advance two z points
            D1 = add2(D1, IAB2); D2 = add2(D2, IAC2); D43 = add2(D43, I432);
            APZ = add2(APZ, DZ2); BPZ = add2(BPZ, DZ2);
            HS = add2(HS, IHS2); VB = add2(VB, IVB2); VC = add2(VC, IVC2);
        }
    }

    // ---- reduce via RED atomics ----
    const int pbase = ((ix * 32 + iy) * 32 + iz0);
    #pragma unroll
    for (int k = 0; k < KPT; ++k)
        atomicMin(&g_md2min[pbase + k], __float_as_uint(md[k]));
    if (par) atomicXor(&g_parity[g], par);
}

__global__ void __launch_bounds__(256)
sdf_finalize(float* __restrict__ out)
{
    int p = blockIdx.x * 256 + threadIdx.x;               // [0, 32768)
    float m = __uint_as_float(g_md2min[p]);
    unsigned par = (g_parity[p >> 4] >> (p & 15)) & 1u;
    out[p] = par ? sqrtf(m) : 0.0f;
}

extern "C" void kernel_launch(void* const* d_in, const int* in_sizes, int n_in,
                              void* d_out, int out_size)
{
    const int* faces = nullptr;
    const float* verts = nullptr;
    for (int i = 0; i < n_in; ++i) {
        if (in_sizes[i] == 3 * N_FACES)   faces = (const int*)d_in[i];
        else if (in_sizes[i] == 3 * 1026) verts = (const float*)d_in[i];
    }
    if (!faces) faces = (const int*)d_in[0];
    if (!verts) verts = (const float*)d_in[1];

    sdf_init<<<N_PTS / 256, 256>>>();
    dim3 grid(N_GROUPS / THREADS, N_CHUNKS);              // 16 x 37 = 592 blocks
    sdf_main<<<grid, THREADS>>>(faces, verts);
    sdf_finalize<<<N_PTS / 256, 256>>>((float*)d_out);
}